// round 10
// baseline (speedup 1.0000x reference)
#include <cuda_runtime.h>
#include <math.h>
#include <stdint.h>

#define NB   262144
#define H1C  128
#define H2C  256
#define H3C  200
#define GC   25
#define DC   4
#define GDC  100

// -------------------------------------------------- pair-interleaved weights
// [kpair][2n + h] = W[n][2*kp + h]
__device__ float g_W2P[64 * 512];     // W2: 64 kp, n=256
__device__ float g_W3P[128 * 448];    // W3: 128 kp, n padded 200->224
__device__ float g_WpP[100 * 256];    // Wp: 100 kp, n padded 100->128

// ------------------------------------------------------------ f32x2 helpers
__device__ __forceinline__ float2 upk2(uint64_t v) {
    float2 r;
    asm("mov.b64 {%0, %1}, %2;" : "=f"(r.x), "=f"(r.y) : "l"(v));
    return r;
}
__device__ __forceinline__ void fma2(uint64_t& d, uint64_t a, uint64_t b) {
    asm("fma.rn.f32x2 %0, %1, %2, %0;" : "+l"(d) : "l"(a), "l"(b));
}

// ------------------------------------------------------------------- prep
__global__ void k_prep(const float* __restrict__ W2, const float* __restrict__ W3,
                       const float* __restrict__ Wp) {
    int stride = gridDim.x * blockDim.x;
    int i0 = blockIdx.x * blockDim.x + threadIdx.x;
    for (int i = i0; i < 64 * 512; i += stride) {
        int kp = i >> 9, rem = i & 511, n = rem >> 1, h = rem & 1;
        g_W2P[i] = W2[n * H1C + 2 * kp + h];
    }
    for (int i = i0; i < 128 * 448; i += stride) {
        int kp = i / 448, rem = i % 448, n = rem >> 1, h = rem & 1;
        g_W3P[i] = (n < 200) ? W3[n * H2C + 2 * kp + h] : 0.f;
    }
    for (int i = i0; i < 100 * 256; i += stride) {
        int kp = i >> 8, rem = i & 255, n = rem >> 1, h = rem & 1;
        g_WpP[i] = (n < 100) ? Wp[n * H3C + 2 * kp + h] : 0.f;
    }
}

// ------------------------------------------------------------- fused kernel
// 64 rows/CTA, 512 threads = 16 warps: rw = wid&7 -> 8-row group,
// half = wid>>3 -> column half. k-split u64 accumulators (acc.x even-k,
// acc.y odd-k). A = broadcast LDS.64 of 2 consecutive k; B = pair-
// interleaved LDS.64 carrying 2 k's. No pk2 splats anywhere.
__global__ __launch_bounds__(512, 1) void k_fused(
        const float* __restrict__ x0,   const float* __restrict__ W1,
        const float* __restrict__ b1,   const float* __restrict__ b2,
        const float* __restrict__ b3,
        const float* __restrict__ gumbel, const float* __restrict__ rnd,
        const float* __restrict__ Wmu,  const float* __restrict__ bmu,
        const float* __restrict__ Wsig, const float* __restrict__ bsig,
        const float* __restrict__ bpai, float* __restrict__ out) {
    extern __shared__ float sm[];
    float* h1s = sm;              // [64][128]
    float* h2s = sm;              // [64][256] overlay
    float* h3s = sm;              // [64][200] overlay
    float* WB  = sm + 16384;      // weight buffer (max 32768 floats)
    float* lps = sm + 41984;      // [64][100]
    __shared__ float xs[64 * 3], W1s[H1C * 3], b1s[H1C], b2s[H2C], b3s[H3C], bps[GDC];
    __shared__ int idxs[256];

    const int tid  = threadIdx.x;
    const int wid  = tid >> 5, lane = tid & 31;
    const int b0   = blockIdx.x * 64;
    const int rw   = wid & 7, half = wid >> 3;
    const int r0   = rw * 8;            // 8 rows per warp

    // ---- stage constants + full W2 pair image (128KB)
    for (int e = tid; e < H1C * 3; e += 512) W1s[e] = W1[e];
    if (tid < H1C) b1s[tid] = b1[tid];
    if (tid < H2C) b2s[tid] = b2[tid];
    if (tid < H3C) b3s[tid] = b3[tid];
    if (tid < GDC) bps[tid] = bpai[tid];
    for (int e = tid; e < 64 * 3; e += 512) xs[e] = x0[(size_t)b0 * 3 + e];
    {
        float4* dst = (float4*)WB;
        const float4* src = (const float4*)g_W2P;
        for (int e = tid; e < 8192; e += 512) dst[e] = src[e];
    }
    __syncthreads();

    // ---- layer 1: h1 = relu(x0 @ W1^T + b1)
    for (int e = tid; e < 64 * H1C; e += 512) {
        int r = e >> 7, j = e & 127;
        float v = fmaf(xs[r * 3 + 0], W1s[j * 3 + 0],
                  fmaf(xs[r * 3 + 1], W1s[j * 3 + 1],
                  fmaf(xs[r * 3 + 2], W1s[j * 3 + 2], b1s[j])));
        h1s[e] = fmaxf(v, 0.f);
    }
    __syncthreads();

    // ---- layer 2: [64 x 256], 64 kp; warp tile 8r x 128n (its half)
    {
        uint64_t acc[8][4];
#pragma unroll
        for (int r = 0; r < 8; r++)
#pragma unroll
            for (int j = 0; j < 4; j++) acc[r][j] = 0ull;

#pragma unroll 2
        for (int kp = 0; kp < 64; kp++) {
            const uint64_t* bp = (const uint64_t*)(WB + kp * 512) + half * 128;
            uint64_t bv0 = bp[lane], bv1 = bp[32 + lane];
            uint64_t bv2 = bp[64 + lane], bv3 = bp[96 + lane];
#pragma unroll
            for (int r = 0; r < 8; r++) {
                uint64_t a2 = *(const uint64_t*)(h1s + (r0 + r) * H1C + 2 * kp);
                fma2(acc[r][0], a2, bv0);
                fma2(acc[r][1], a2, bv1);
                fma2(acc[r][2], a2, bv2);
                fma2(acc[r][3], a2, bv3);
            }
        }
        __syncthreads();   // reads of h1s/WB done before overlay

        // epilogue: h2 = relu(acc.x + acc.y + b2); n = 128*half + lane + 32j
#pragma unroll
        for (int r = 0; r < 8; r++)
#pragma unroll
            for (int j = 0; j < 4; j++) {
                int n = 128 * half + 32 * j + lane;
                float2 v = upk2(acc[r][j]);
                h2s[(r0 + r) * H2C + n] = fmaxf(v.x + v.y + b2s[n], 0.f);
            }
        __syncthreads();
    }

    // ---- layer 3: [64 x 200(224)], 128 kp in 2 panels of 64
    // half0: 4 col-groups (cols 0..127); half1: 3 groups (cols 128..223 padded)
    {
        uint64_t acc[8][4];
#pragma unroll
        for (int r = 0; r < 8; r++)
#pragma unroll
            for (int j = 0; j < 4; j++) acc[r][j] = 0ull;
        const int ng = half ? 3 : 4;

        for (int pan = 0; pan < 2; pan++) {
            {
                float4* dst = (float4*)WB;
                const float4* src = (const float4*)(g_W3P + pan * 28672);
                for (int e = tid; e < 7168; e += 512) dst[e] = src[e];
            }
            __syncthreads();
#pragma unroll 2
            for (int kp = 0; kp < 64; kp++) {
                const uint64_t* bp = (const uint64_t*)(WB + kp * 448) + half * 128;
                uint64_t bv[4];
#pragma unroll
                for (int j = 0; j < 4; j++)
                    bv[j] = (j < ng) ? bp[32 * j + lane] : 0ull;
#pragma unroll
                for (int r = 0; r < 8; r++) {
                    uint64_t a2 = *(const uint64_t*)(h2s + (r0 + r) * H2C
                                                     + pan * 128 + 2 * kp);
                    fma2(acc[r][0], a2, bv[0]);
                    fma2(acc[r][1], a2, bv[1]);
                    fma2(acc[r][2], a2, bv[2]);
                    if (!half) fma2(acc[r][3], a2, bv[3]);
                }
            }
            __syncthreads();   // panel reads done before reload / overlay
        }

        // epilogue: h3 = relu(acc.x + acc.y + b3); n = 128*half + lane + 32j
#pragma unroll
        for (int r = 0; r < 8; r++)
#pragma unroll
            for (int j = 0; j < 4; j++) {
                int n = 128 * half + 32 * j + lane;
                if (j < ng && n < H3C) {
                    float2 v = upk2(acc[r][j]);
                    h3s[(r0 + r) * H3C + n] = fmaxf(v.x + v.y + b3s[n], 0.f);
                }
            }
        __syncthreads();
    }

    // ---- pi GEMM: [64 x 100(128)], 100 kp, full weight image
    {
        {
            float4* dst = (float4*)WB;
            const float4* src = (const float4*)g_WpP;
            for (int e = tid; e < 6400; e += 512) dst[e] = src[e];
        }
        __syncthreads();

        uint64_t acc[8][2];
#pragma unroll
        for (int r = 0; r < 8; r++) { acc[r][0] = 0ull; acc[r][1] = 0ull; }

#pragma unroll 2
        for (int kp = 0; kp < 100; kp++) {
            const uint64_t* bp = (const uint64_t*)(WB + kp * 256) + half * 64;
            uint64_t bv0 = bp[lane], bv1 = bp[32 + lane];
#pragma unroll
            for (int r = 0; r < 8; r++) {
                uint64_t a2 = *(const uint64_t*)(h3s + (r0 + r) * H3C + 2 * kp);
                fma2(acc[r][0], a2, bv0);
                fma2(acc[r][1], a2, bv1);
            }
        }

        // lps = log(|pi + b| + eps); n = 64*half + lane + 32j  (n < 100)
#pragma unroll
        for (int r = 0; r < 8; r++)
#pragma unroll
            for (int j = 0; j < 2; j++) {
                int n = 64 * half + 32 * j + lane;
                if (n < GDC) {
                    float2 v = upk2(acc[r][j]);
                    lps[(r0 + r) * GDC + n] = logf(fabsf(v.x + v.y + bps[n]) + 1e-12f);
                }
            }
        __syncthreads();
    }

    // ---- Gumbel-argmax per (row, d): threads 0..255
    if (tid < 256) {
        int r = tid >> 2, d = tid & 3;
        const float* gp = gumbel + (size_t)(b0 + r) * GDC + d;
        float best = -1e30f;
        int bg = 0;
#pragma unroll
        for (int g = 0; g < GC; g++) {
            float v = lps[r * GDC + g * 4 + d] + gp[g * 4];
            if (v > best) { best = v; bg = g; }
        }
        idxs[tid] = bg;
    }
    __syncthreads();

    // ---- selection: 8 lanes per pair, 4 pairs per warp per iter, 4 iters
    const int sl = lane & 7, grp = lane >> 3;
    for (int it = 0; it < 4; it++) {
        int pp = wid * 16 + it * 4 + grp;        // pair index in [0,256)
        int r = pp >> 2, d = pp & 3;
        int head = idxs[pp] * 4 + d;
        const float4* wm = (const float4*)(Wmu  + (size_t)head * H3C);
        const float4* ws = (const float4*)(Wsig + (size_t)head * H3C);
        const float4* hv = (const float4*)(h3s + r * H3C);

        float smu = 0.f, ssg = 0.f;
#pragma unroll
        for (int j = 0; j < 6; j++) {
            int i4 = sl + 8 * j;
            float4 h = hv[i4];
            float4 m = wm[i4];
            float4 s = ws[i4];
            smu = fmaf(h.x, m.x, fmaf(h.y, m.y, fmaf(h.z, m.z, fmaf(h.w, m.w, smu))));
            ssg = fmaf(h.x, s.x, fmaf(h.y, s.y, fmaf(h.z, s.z, fmaf(h.w, s.w, ssg))));
        }
        if (sl < 2) {
            int i4 = 48 + sl;
            float4 h = hv[i4];
            float4 m = wm[i4];
            float4 s = ws[i4];
            smu = fmaf(h.x, m.x, fmaf(h.y, m.y, fmaf(h.z, m.z, fmaf(h.w, m.w, smu))));
            ssg = fmaf(h.x, s.x, fmaf(h.y, s.y, fmaf(h.z, s.z, fmaf(h.w, s.w, ssg))));
        }
#pragma unroll
        for (int off = 4; off > 0; off >>= 1) {
            smu += __shfl_xor_sync(0xffffffffu, smu, off);
            ssg += __shfl_xor_sync(0xffffffffu, ssg, off);
        }
        if (sl == 0) {
            float mu = smu + bmu[head];
            float sg = fabsf(ssg + bsig[head]);
            size_t oi = (size_t)(b0 + r) * DC + d;
            out[oi] = rnd[oi] * sg + mu;
        }
    }
}

// ---------------------------------------------------------------- launch
extern "C" void kernel_launch(void* const* d_in, const int* in_sizes, int n_in,
                              void* d_out, int out_size) {
    const float* x0   = (const float*)d_in[0];
    const float* rnd  = (const float*)d_in[1];
    const float* gum  = (const float*)d_in[2];
    const float* W1   = (const float*)d_in[3];
    const float* b1   = (const float*)d_in[4];
    const float* W2   = (const float*)d_in[5];
    const float* b2   = (const float*)d_in[6];
    const float* W3   = (const float*)d_in[7];
    const float* b3   = (const float*)d_in[8];
    const float* Wmu  = (const float*)d_in[9];
    const float* bmu  = (const float*)d_in[10];
    const float* Wsig = (const float*)d_in[11];
    const float* bsig = (const float*)d_in[12];
    const float* Wpai = (const float*)d_in[13];
    const float* bpai = (const float*)d_in[14];
    float* out = (float*)d_out;

    const size_t smF = 49152 * sizeof(float);   // 196608 B

    cudaFuncSetAttribute(k_fused, cudaFuncAttributeMaxDynamicSharedMemorySize, (int)smF);

    k_prep <<<64, 256>>>(W2, W3, Wpai);
    k_fused<<<NB / 64, 512, smF>>>(x0, W1, b1, b2, b3,
                                   gum, rnd, Wmu, bmu, Wsig, bsig, bpai, out);
}

// round 11
// speedup vs baseline: 1.0225x; 1.0225x over previous
#include <cuda_runtime.h>
#include <math.h>
#include <stdint.h>

#define NB   262144
#define H1C  128
#define H2C  256
#define H3C  200
#define GC   25
#define DC   4
#define GDC  100

// -------------------------------------------------- pair-interleaved weights
// [kpair][2n + h] = W[n][2*kp + h]
__device__ float g_W2P[64 * 512];     // W2: 64 kp, n=256
__device__ float g_W3P[128 * 448];    // W3: 128 kp, n padded 200->224
__device__ float g_WpP[100 * 256];    // Wp: 100 kp, n padded 100->128

// ------------------------------------------------------------ f32x2 helpers
__device__ __forceinline__ float2 upk2(uint64_t v) {
    float2 r;
    asm("mov.b64 {%0, %1}, %2;" : "=f"(r.x), "=f"(r.y) : "l"(v));
    return r;
}
__device__ __forceinline__ void fma2(uint64_t& d, uint64_t a, uint64_t b) {
    asm("fma.rn.f32x2 %0, %1, %2, %0;" : "+l"(d) : "l"(a), "l"(b));
}

// ------------------------------------------------------------------- prep
__global__ void k_prep(const float* __restrict__ W2, const float* __restrict__ W3,
                       const float* __restrict__ Wp) {
    int stride = gridDim.x * blockDim.x;
    int i0 = blockIdx.x * blockDim.x + threadIdx.x;
    for (int i = i0; i < 64 * 512; i += stride) {
        int kp = i >> 9, rem = i & 511, n = rem >> 1, h = rem & 1;
        g_W2P[i] = W2[n * H1C + 2 * kp + h];
    }
    for (int i = i0; i < 128 * 448; i += stride) {
        int kp = i / 448, rem = i % 448, n = rem >> 1, h = rem & 1;
        g_W3P[i] = (n < 200) ? W3[n * H2C + 2 * kp + h] : 0.f;
    }
    for (int i = i0; i < 100 * 256; i += stride) {
        int kp = i >> 8, rem = i & 255, n = rem >> 1, h = rem & 1;
        g_WpP[i] = (n < 100) ? Wp[n * H3C + 2 * kp + h] : 0.f;
    }
}

// ------------------------------------------------------------- fused kernel
// 64 rows/CTA, 256 threads (8 warps x 8 rows), 2 CTAs/SM.
// k-split u64 accumulators; column halves sequential with register parking.
// smem: ACT [0,16384) h1->h2->h3 overlays; WB [16384,24576) (lps overlay).
__global__ __launch_bounds__(256, 2) void k_fused(
        const float* __restrict__ x0,   const float* __restrict__ W1,
        const float* __restrict__ b1,   const float* __restrict__ b2,
        const float* __restrict__ b3,
        const float* __restrict__ gumbel, const float* __restrict__ rnd,
        const float* __restrict__ Wmu,  const float* __restrict__ bmu,
        const float* __restrict__ Wsig, const float* __restrict__ bsig,
        const float* __restrict__ bpai, float* __restrict__ out) {
    extern __shared__ float sm[];
    float* h1s = sm;              // [64][128]
    float* h2s = sm;              // [64][256] overlay
    float* h3s = sm;              // [64][200] overlay
    float* WB  = sm + 16384;      // 8192-float weight panel buffer
    float* lps = sm + 16384;      // [64][100] overlays WB after pi GEMM
    __shared__ float xs[64 * 3], W1s[H1C * 3], b1s[H1C], b2s[H2C], b3s[H3C], bps[GDC];
    __shared__ int idxs[256];

    const int tid  = threadIdx.x;
    const int wid  = tid >> 5, lane = tid & 31;
    const int b0   = blockIdx.x * 64;
    const int r0   = wid * 8;

    // ---- stage constants
    for (int e = tid; e < H1C * 3; e += 256) W1s[e] = W1[e];
    if (tid < H1C) b1s[tid] = b1[tid];
    b2s[tid] = b2[tid];
    for (int e = tid; e < H3C; e += 256) b3s[e] = b3[e];
    for (int e = tid; e < GDC; e += 256) bps[e] = bpai[e];
    for (int e = tid; e < 64 * 3; e += 256) xs[e] = x0[(size_t)b0 * 3 + e];
    __syncthreads();

    // ---- layer 1: h1 = relu(x0 @ W1^T + b1)
    for (int e = tid; e < 64 * H1C; e += 256) {
        int r = e >> 7, j = e & 127;
        float v = fmaf(xs[r * 3 + 0], W1s[j * 3 + 0],
                  fmaf(xs[r * 3 + 1], W1s[j * 3 + 1],
                  fmaf(xs[r * 3 + 2], W1s[j * 3 + 2], b1s[j])));
        h1s[e] = fmaxf(v, 0.f);
    }
    // (h1s consumed only after the first panel-staging sync below)

    // =========================== layer 2: [64 x 256], K=128 (64 kp) =======
    float park2[8][4];
    {
        // ---- half 0: cols 0..127
        uint64_t acc[8][4];
#pragma unroll
        for (int r = 0; r < 8; r++)
#pragma unroll
            for (int j = 0; j < 4; j++) acc[r][j] = 0ull;
        for (int pan = 0; pan < 4; pan++) {
            __syncthreads();
            {
                float4* dst = (float4*)WB;
                const float4* src = (const float4*)(g_W2P + pan * 8192);
                for (int e = tid; e < 2048; e += 256) dst[e] = src[e];
            }
            __syncthreads();
            const uint64_t* bptr = (const uint64_t*)WB + lane;
            const float*    aptr = h1s + r0 * H1C + pan * 32;
#pragma unroll 4
            for (int kp = 0; kp < 16; kp++) {
                uint64_t bv0 = bptr[0], bv1 = bptr[32];
                uint64_t bv2 = bptr[64], bv3 = bptr[96];
#pragma unroll
                for (int r = 0; r < 8; r++) {
                    uint64_t a2 = *(const uint64_t*)(aptr + r * H1C);
                    fma2(acc[r][0], a2, bv0);
                    fma2(acc[r][1], a2, bv1);
                    fma2(acc[r][2], a2, bv2);
                    fma2(acc[r][3], a2, bv3);
                }
                bptr += 256; aptr += 2;
            }
        }
#pragma unroll
        for (int r = 0; r < 8; r++)
#pragma unroll
            for (int j = 0; j < 4; j++) {
                float2 v = upk2(acc[r][j]);
                park2[r][j] = fmaxf(v.x + v.y + b2s[32 * j + lane], 0.f);
            }
    }
    {
        // ---- half 1: cols 128..255
        uint64_t acc[8][4];
#pragma unroll
        for (int r = 0; r < 8; r++)
#pragma unroll
            for (int j = 0; j < 4; j++) acc[r][j] = 0ull;
        for (int pan = 0; pan < 4; pan++) {
            __syncthreads();
            {
                float4* dst = (float4*)WB;
                const float4* src = (const float4*)(g_W2P + pan * 8192);
                for (int e = tid; e < 2048; e += 256) dst[e] = src[e];
            }
            __syncthreads();
            const uint64_t* bptr = (const uint64_t*)WB + 128 + lane;
            const float*    aptr = h1s + r0 * H1C + pan * 32;
#pragma unroll 4
            for (int kp = 0; kp < 16; kp++) {
                uint64_t bv0 = bptr[0], bv1 = bptr[32];
                uint64_t bv2 = bptr[64], bv3 = bptr[96];
#pragma unroll
                for (int r = 0; r < 8; r++) {
                    uint64_t a2 = *(const uint64_t*)(aptr + r * H1C);
                    fma2(acc[r][0], a2, bv0);
                    fma2(acc[r][1], a2, bv1);
                    fma2(acc[r][2], a2, bv2);
                    fma2(acc[r][3], a2, bv3);
                }
                bptr += 256; aptr += 2;
            }
        }
        __syncthreads();   // all warps done reading h1s & WB
        // write full h2 (overlays h1s)
#pragma unroll
        for (int r = 0; r < 8; r++)
#pragma unroll
            for (int j = 0; j < 4; j++) {
                int n0 = 32 * j + lane, n1 = 128 + 32 * j + lane;
                h2s[(r0 + r) * H2C + n0] = park2[r][j];
                float2 v = upk2(acc[r][j]);
                h2s[(r0 + r) * H2C + n1] = fmaxf(v.x + v.y + b2s[n1], 0.f);
            }
        __syncthreads();
    }

    // ====================== layer 3: [64 x 200(224)], K=256 (128 kp) ======
    float park3[8][3];
    {
        // ---- half A: cols 128..223 (3 col-groups)
        uint64_t acc[8][3];
#pragma unroll
        for (int r = 0; r < 8; r++)
#pragma unroll
            for (int j = 0; j < 3; j++) acc[r][j] = 0ull;
        for (int pan = 0; pan < 8; pan++) {
            __syncthreads();
            {
                float4* dst = (float4*)WB;
                const float4* src = (const float4*)(g_W3P + pan * 7168);
                for (int e = tid; e < 1792; e += 256) dst[e] = src[e];
            }
            __syncthreads();
            const uint64_t* bptr = (const uint64_t*)WB + 128 + lane;
            const float*    aptr = h2s + r0 * H2C + pan * 32;
#pragma unroll 4
            for (int kp = 0; kp < 16; kp++) {
                uint64_t bv0 = bptr[0], bv1 = bptr[32], bv2 = bptr[64];
#pragma unroll
                for (int r = 0; r < 8; r++) {
                    uint64_t a2 = *(const uint64_t*)(aptr + r * H2C);
                    fma2(acc[r][0], a2, bv0);
                    fma2(acc[r][1], a2, bv1);
                    fma2(acc[r][2], a2, bv2);
                }
                bptr += 224; aptr += 2;
            }
        }
#pragma unroll
        for (int r = 0; r < 8; r++)
#pragma unroll
            for (int j = 0; j < 3; j++) {
                int n = 128 + 32 * j + lane;
                float2 v = upk2(acc[r][j]);
                park3[r][j] = fmaxf(v.x + v.y + ((n < H3C) ? b3s[n] : 0.f), 0.f);
            }
    }
    {
        // ---- half B: cols 0..127 (4 col-groups)
        uint64_t acc[8][4];
#pragma unroll
        for (int r = 0; r < 8; r++)
#pragma unroll
            for (int j = 0; j < 4; j++) acc[r][j] = 0ull;
        for (int pan = 0; pan < 8; pan++) {
            __syncthreads();
            {
                float4* dst = (float4*)WB;
                const float4* src = (const float4*)(g_W3P + pan * 7168);
                for (int e = tid; e < 1792; e += 256) dst[e] = src[e];
            }
            __syncthreads();
            const uint64_t* bptr = (const uint64_t*)WB + lane;
            const float*    aptr = h2s + r0 * H2C + pan * 32;
#pragma unroll 4
            for (int kp = 0; kp < 16; kp++) {
                uint64_t bv0 = bptr[0], bv1 = bptr[32];
                uint64_t bv2 = bptr[64], bv3 = bptr[96];
#pragma unroll
                for (int r = 0; r < 8; r++) {
                    uint64_t a2 = *(const uint64_t*)(aptr + r * H2C);
                    fma2(acc[r][0], a2, bv0);
                    fma2(acc[r][1], a2, bv1);
                    fma2(acc[r][2], a2, bv2);
                    fma2(acc[r][3], a2, bv3);
                }
                bptr += 224; aptr += 2;
            }
        }
        __syncthreads();   // all warps done reading h2s & WB
        // write h3 (overlays h2s): cols 0..127 from acc, 128..199 from park
#pragma unroll
        for (int r = 0; r < 8; r++) {
#pragma unroll
            for (int j = 0; j < 4; j++) {
                int n = 32 * j + lane;
                float2 v = upk2(acc[r][j]);
                h3s[(r0 + r) * H3C + n] = fmaxf(v.x + v.y + b3s[n], 0.f);
            }
#pragma unroll
            for (int j = 0; j < 3; j++) {
                int n = 128 + 32 * j + lane;
                if (n < H3C) h3s[(r0 + r) * H3C + n] = park3[r][j];
            }
        }
        __syncthreads();
    }

    // =================== pi GEMM: [64 x 100(128)], K=200 (100 kp) =========
    {
        uint64_t acc[8][4];
#pragma unroll
        for (int r = 0; r < 8; r++)
#pragma unroll
            for (int j = 0; j < 4; j++) acc[r][j] = 0ull;

        for (int pan = 0; pan < 4; pan++) {
            const int kpn = (pan < 3) ? 32 : 4;     // 3*32 + 4 = 100 kp
            __syncthreads();
            {
                float4* dst = (float4*)WB;
                const float4* src = (const float4*)(g_WpP + pan * 8192);
                int n4 = kpn * 64;                   // kp * 256 floats / 4
                for (int e = tid; e < n4; e += 256) dst[e] = src[e];
            }
            __syncthreads();
            const uint64_t* bptr = (const uint64_t*)WB + lane;
            const float*    aptr = h3s + r0 * H3C + pan * 64;
            for (int kp = 0; kp < kpn; kp++) {
                uint64_t bv0 = bptr[0], bv1 = bptr[32];
                uint64_t bv2 = bptr[64], bv3 = bptr[96];
#pragma unroll
                for (int r = 0; r < 8; r++) {
                    uint64_t a2 = *(const uint64_t*)(aptr + r * H3C);
                    fma2(acc[r][0], a2, bv0);
                    fma2(acc[r][1], a2, bv1);
                    fma2(acc[r][2], a2, bv2);
                    fma2(acc[r][3], a2, bv3);
                }
                bptr += 128; aptr += 2;
            }
        }
        __syncthreads();   // pi reads of WB done -> lps may overlay WB
        // lps = log(|pi + b| + eps); cols n = 32j + lane < 100
#pragma unroll
        for (int r = 0; r < 8; r++)
#pragma unroll
            for (int j = 0; j < 4; j++) {
                int n = 32 * j + lane;
                if (n < GDC) {
                    float2 v = upk2(acc[r][j]);
                    lps[(r0 + r) * GDC + n] = logf(fabsf(v.x + v.y + bps[n]) + 1e-12f);
                }
            }
        __syncthreads();
    }

    // ---- Gumbel-argmax per (row, d)
    {
        int r = tid >> 2, d = tid & 3;
        const float* gp = gumbel + (size_t)(b0 + r) * GDC + d;
        float best = -1e30f;
        int bg = 0;
#pragma unroll
        for (int g = 0; g < GC; g++) {
            float v = lps[r * GDC + g * 4 + d] + gp[g * 4];
            if (v > best) { best = v; bg = g; }
        }
        idxs[tid] = bg;
    }
    __syncthreads();

    // ---- selection: 8 lanes per pair, 4 pairs per warp per iter, 8 iters
    const int sl = lane & 7, grp = lane >> 3;
    for (int it = 0; it < 8; it++) {
        int pp = wid * 32 + it * 4 + grp;        // pair index in [0,256)
        int r = pp >> 2, d = pp & 3;
        int head = idxs[pp] * 4 + d;
        const float4* wm = (const float4*)(Wmu  + (size_t)head * H3C);
        const float4* ws = (const float4*)(Wsig + (size_t)head * H3C);
        const float4* hv = (const float4*)(h3s + r * H3C);

        float smu = 0.f, ssg = 0.f;
#pragma unroll
        for (int j = 0; j < 6; j++) {
            int i4 = sl + 8 * j;
            float4 h = hv[i4];
            float4 m = wm[i4];
            float4 s = ws[i4];
            smu = fmaf(h.x, m.x, fmaf(h.y, m.y, fmaf(h.z, m.z, fmaf(h.w, m.w, smu))));
            ssg = fmaf(h.x, s.x, fmaf(h.y, s.y, fmaf(h.z, s.z, fmaf(h.w, s.w, ssg))));
        }
        if (sl < 2) {
            int i4 = 48 + sl;
            float4 h = hv[i4];
            float4 m = wm[i4];
            float4 s = ws[i4];
            smu = fmaf(h.x, m.x, fmaf(h.y, m.y, fmaf(h.z, m.z, fmaf(h.w, m.w, smu))));
            ssg = fmaf(h.x, s.x, fmaf(h.y, s.y, fmaf(h.z, s.z, fmaf(h.w, s.w, ssg))));
        }
#pragma unroll
        for (int off = 4; off > 0; off >>= 1) {
            smu += __shfl_xor_sync(0xffffffffu, smu, off);
            ssg += __shfl_xor_sync(0xffffffffu, ssg, off);
        }
        if (sl == 0) {
            float mu = smu + bmu[head];
            float sg = fabsf(ssg + bsig[head]);
            size_t oi = (size_t)(b0 + r) * DC + d;
            out[oi] = rnd[oi] * sg + mu;
        }
    }
}

// ---------------------------------------------------------------- launch
extern "C" void kernel_launch(void* const* d_in, const int* in_sizes, int n_in,
                              void* d_out, int out_size) {
    const float* x0   = (const float*)d_in[0];
    const float* rnd  = (const float*)d_in[1];
    const float* gum  = (const float*)d_in[2];
    const float* W1   = (const float*)d_in[3];
    const float* b1   = (const float*)d_in[4];
    const float* W2   = (const float*)d_in[5];
    const float* b2   = (const float*)d_in[6];
    const float* W3   = (const float*)d_in[7];
    const float* b3   = (const float*)d_in[8];
    const float* Wmu  = (const float*)d_in[9];
    const float* bmu  = (const float*)d_in[10];
    const float* Wsig = (const float*)d_in[11];
    const float* bsig = (const float*)d_in[12];
    const float* Wpai = (const float*)d_in[13];
    const float* bpai = (const float*)d_in[14];
    float* out = (float*)d_out;

    const size_t smF = 24576 * sizeof(float);   // 98304 B -> 2 CTAs/SM

    cudaFuncSetAttribute(k_fused, cudaFuncAttributeMaxDynamicSharedMemorySize, (int)smF);

    k_prep <<<64, 256>>>(W2, W3, Wpai);
    k_fused<<<NB / 64, 256, smF>>>(x0, W1, b1, b2, b3,
                                   gum, rnd, Wmu, bmu, Wsig, bsig, bpai, out);
}

// round 12
// speedup vs baseline: 1.3501x; 1.3204x over previous
#include <cuda_runtime.h>
#include <math.h>
#include <stdint.h>

#define NB   262144
#define H1C  128
#define H2C  256
#define H3C  200
#define GC   25
#define DC   4
#define GDC  100

// ---------------------------------------------------------- device scratch
__device__ float g_W2T[128 * 256];      // [k][n]
__device__ float g_W3T[256 * 208];      // [k][n], n padded 200->208
__device__ float g_WpT[200 * 104];      // [k][n], n padded 100->104

// ------------------------------------------------------------ f32x2 helpers
__device__ __forceinline__ uint64_t pk2(float x, float y) {
    uint64_t r;
    asm("mov.b64 %0, {%1, %2};" : "=l"(r) : "f"(x), "f"(y));
    return r;
}
__device__ __forceinline__ float2 upk2(uint64_t v) {
    float2 r;
    asm("mov.b64 {%0, %1}, %2;" : "=f"(r.x), "=f"(r.y) : "l"(v));
    return r;
}
__device__ __forceinline__ void fma2(uint64_t& d, uint64_t a, uint64_t b) {
    asm("fma.rn.f32x2 %0, %1, %2, %0;" : "+l"(d) : "l"(a), "l"(b));
}

// ------------------------------------------------------------ cp.async
__device__ __forceinline__ void cpa16(float4* dst_smem, const float4* src) {
    uint32_t d = (uint32_t)__cvta_generic_to_shared(dst_smem);
    asm volatile("cp.async.ca.shared.global [%0], [%1], 16;"
                 :: "r"(d), "l"(src) : "memory");
}
#define CPA_COMMIT() asm volatile("cp.async.commit_group;" ::: "memory")
#define CPA_WAIT0()  asm volatile("cp.async.wait_group 0;" ::: "memory")

__device__ __forceinline__ void stage_async(float* dst, const float* src,
                                            int nf4, int tid) {
    float4* d = (float4*)dst;
    const float4* s = (const float4*)src;
    for (int e = tid; e < nf4; e += 256) cpa16(d + e, s + e);
}

// ------------------------------------------------------------------- prep
__global__ void k_prep(const float* __restrict__ W2, const float* __restrict__ W3,
                       const float* __restrict__ Wp) {
    int stride = gridDim.x * blockDim.x;
    int i0 = blockIdx.x * blockDim.x + threadIdx.x;
    for (int e = i0; e < 128 * 256; e += stride) {
        int k = e >> 8, n = e & 255;
        g_W2T[e] = W2[n * H1C + k];
    }
    for (int e = i0; e < 256 * 208; e += stride) {
        int k = e / 208, n = e % 208;
        g_W3T[e] = (n < 200) ? W3[n * H2C + k] : 0.f;
    }
    for (int e = i0; e < 200 * 104; e += stride) {
        int k = e / 104, n = e % 104;
        g_WpT[e] = (n < 100) ? Wp[n * H3C + k] : 0.f;
    }
}

// ------------------------------------------------------------- fused kernel
// 64 rows/CTA, 256 threads (8 warps x 8 rows), 2 CTAs/SM.
// Col-pair u64 accumulators (R7); cp.async double-buffered weight panels.
// smem (floats): ACT [0,16384) h1->h2->h3; WB0 @16384 (4160); WB1 @20544
// (4160); lps overlays WB @16384 after pi. Total 24704 floats.
__global__ __launch_bounds__(256, 2) void k_fused(
        const float* __restrict__ x0,   const float* __restrict__ W1,
        const float* __restrict__ b1,   const float* __restrict__ b2,
        const float* __restrict__ b3,
        const float* __restrict__ gumbel, const float* __restrict__ rnd,
        const float* __restrict__ Wmu,  const float* __restrict__ bmu,
        const float* __restrict__ Wsig, const float* __restrict__ bsig,
        const float* __restrict__ bpai, float* __restrict__ out) {
    extern __shared__ float sm[];
    float* h1s = sm;
    float* h2s = sm;
    float* h3s = sm;
    float* WBa = sm + 16384;
    float* WBb = sm + 20544;
    float* lps = sm + 16384;
    __shared__ float xs[64 * 3], W1s[H1C * 3], b1s[H1C], b2s[H2C], b3s[H3C], bps[GDC];
    __shared__ int idxs[256];

    const int tid  = threadIdx.x;
    const int wid  = tid >> 5, lane = tid & 31;
    const int b0   = blockIdx.x * 64;
    const int r0   = wid * 8;

    // ---- stage constants; prefetch W2 panel 0
    for (int e = tid; e < H1C * 3; e += 256) W1s[e] = W1[e];
    if (tid < H1C) b1s[tid] = b1[tid];
    b2s[tid] = b2[tid];
    for (int e = tid; e < H3C; e += 256) b3s[e] = b3[e];
    for (int e = tid; e < GDC; e += 256) bps[e] = bpai[e];
    for (int e = tid; e < 64 * 3; e += 256) xs[e] = x0[(size_t)b0 * 3 + e];
    stage_async(WBa, g_W2T, 1024, tid);
    CPA_COMMIT();
    __syncthreads();   // constants ready

    // ---- layer 1: h1 = relu(x0 @ W1^T + b1)
    for (int e = tid; e < 64 * H1C; e += 256) {
        int r = e >> 7, j = e & 127;
        float v = fmaf(xs[r * 3 + 0], W1s[j * 3 + 0],
                  fmaf(xs[r * 3 + 1], W1s[j * 3 + 1],
                  fmaf(xs[r * 3 + 2], W1s[j * 3 + 2], b1s[j])));
        h1s[e] = fmaxf(v, 0.f);
    }

    // =========== layer 2: [64 x 256], K=128, 8 panels of 16 k ============
    uint64_t acc2[8][4];
#pragma unroll
    for (int r = 0; r < 8; r++)
#pragma unroll
        for (int j = 0; j < 4; j++) acc2[r][j] = 0ull;

    for (int p = 0; p < 8; p++) {
        CPA_WAIT0();
        __syncthreads();   // panel p ready; (p=0: h1s ready too)
        if (p < 7) {
            stage_async((p & 1) ? WBa : WBb, g_W2T + (p + 1) * 16 * 256, 1024, tid);
            CPA_COMMIT();
        }
        const float* wb = (p & 1) ? WBb : WBa;
        const uint64_t* bptr = (const uint64_t*)wb + lane;
        const float*    aptr = h1s + r0 * H1C + p * 16;
#pragma unroll 4
        for (int k = 0; k < 16; k++) {
            uint64_t bv0 = bptr[0], bv1 = bptr[32];
            uint64_t bv2 = bptr[64], bv3 = bptr[96];
#pragma unroll
            for (int r = 0; r < 8; r++) {
                float av = aptr[r * H1C];
                uint64_t a2 = pk2(av, av);
                fma2(acc2[r][0], a2, bv0);
                fma2(acc2[r][1], a2, bv1);
                fma2(acc2[r][2], a2, bv2);
                fma2(acc2[r][3], a2, bv3);
            }
            bptr += 128; aptr += 1;
        }
    }
    __syncthreads();   // l2 compute done -> safe to overlay h1s & stage l3

    stage_async(WBa, g_W3T, 832, tid);   // l3 panel 0 (WBa last read panel 6)
    CPA_COMMIT();

    // epilogue: h2 = relu(acc + b2); cols n = 64j + 2*lane
#pragma unroll
    for (int r = 0; r < 8; r++)
#pragma unroll
        for (int j = 0; j < 4; j++) {
            int n = 64 * j + 2 * lane;
            float2 v = upk2(acc2[r][j]);
            v.x = fmaxf(v.x + b2s[n],     0.f);
            v.y = fmaxf(v.y + b2s[n + 1], 0.f);
            *(float2*)(h2s + (r0 + r) * H2C + n) = v;
        }

    // ====== layer 3: [64 x 200(208)], K=256, 16 panels of 16 k ===========
    uint64_t acc3[8][4];
#pragma unroll
    for (int r = 0; r < 8; r++)
#pragma unroll
        for (int j = 0; j < 4; j++) acc3[r][j] = 0ull;

    for (int p = 0; p < 16; p++) {
        CPA_WAIT0();
        __syncthreads();   // panel p ready; (p=0: h2s ready too)
        if (p < 15) {
            stage_async((p & 1) ? WBa : WBb, g_W3T + (p + 1) * 16 * 208, 832, tid);
            CPA_COMMIT();
        }
        const float* wb = (p & 1) ? WBb : WBa;
        const uint64_t* bptr = (const uint64_t*)wb + lane;
        const float*    aptr = h2s + r0 * H2C + p * 16;
#pragma unroll 4
        for (int k = 0; k < 16; k++) {
            uint64_t bv0 = bptr[0], bv1 = bptr[32], bv2 = bptr[64];
            uint64_t bv3 = (lane < 8) ? bptr[96] : 0ull;
#pragma unroll
            for (int r = 0; r < 8; r++) {
                float av = aptr[r * H2C];
                uint64_t a2 = pk2(av, av);
                fma2(acc3[r][0], a2, bv0);
                fma2(acc3[r][1], a2, bv1);
                fma2(acc3[r][2], a2, bv2);
                fma2(acc3[r][3], a2, bv3);
            }
            bptr += 104; aptr += 1;
        }
    }
    __syncthreads();   // l3 compute done -> safe to overlay h2s & stage pi

    stage_async(WBa, g_WpT, 1040, tid);  // pi panel 0 (WBa last read panel 14)
    CPA_COMMIT();

    // epilogue: h3 = relu(acc + b3); cols n = 64j + 2*lane (< 200)
#pragma unroll
    for (int r = 0; r < 8; r++) {
#pragma unroll
        for (int j = 0; j < 3; j++) {
            int n = 64 * j + 2 * lane;
            float2 v = upk2(acc3[r][j]);
            v.x = fmaxf(v.x + b3s[n],     0.f);
            v.y = fmaxf(v.y + b3s[n + 1], 0.f);
            *(float2*)(h3s + (r0 + r) * H3C + n) = v;
        }
        if (lane < 4) {
            int n = 192 + 2 * lane;
            float2 v = upk2(acc3[r][3]);
            v.x = fmaxf(v.x + b3s[n],     0.f);
            v.y = fmaxf(v.y + b3s[n + 1], 0.f);
            *(float2*)(h3s + (r0 + r) * H3C + n) = v;
        }
    }

    // ============ pi GEMM: [64 x 100(104)], K=200, 5 panels of 40 k =======
    uint64_t accp[8][2];
#pragma unroll
    for (int r = 0; r < 8; r++) { accp[r][0] = 0ull; accp[r][1] = 0ull; }

    for (int p = 0; p < 5; p++) {
        CPA_WAIT0();
        __syncthreads();   // panel p ready; (p=0: h3s ready too)
        if (p < 4) {
            stage_async((p & 1) ? WBa : WBb, g_WpT + (p + 1) * 40 * 104, 1040, tid);
            CPA_COMMIT();
        }
        const float* wb = (p & 1) ? WBb : WBa;
        const uint64_t* bptr = (const uint64_t*)wb + lane;
        const float*    aptr = h3s + r0 * H3C + p * 40;
#pragma unroll 4
        for (int k = 0; k < 40; k++) {
            uint64_t bv0 = bptr[0];
            uint64_t bv1 = (lane < 20) ? bptr[32] : 0ull;
#pragma unroll
            for (int r = 0; r < 8; r++) {
                float av = aptr[r * H3C];
                uint64_t a2 = pk2(av, av);
                fma2(accp[r][0], a2, bv0);
                fma2(accp[r][1], a2, bv1);
            }
            bptr += 52; aptr += 1;
        }
    }
    __syncthreads();   // pi reads of WB done -> lps may overlay WB

    // lps = log(|pi + b| + eps); cols n = 64j + 2*lane (< 100)
#pragma unroll
    for (int r = 0; r < 8; r++) {
        {
            int n = 2 * lane;
            float2 v = upk2(accp[r][0]);
            float2 o;
            o.x = logf(fabsf(v.x + bps[n])     + 1e-12f);
            o.y = logf(fabsf(v.y + bps[n + 1]) + 1e-12f);
            *(float2*)(lps + (r0 + r) * GDC + n) = o;
        }
        if (lane < 18) {
            int n = 64 + 2 * lane;
            float2 v = upk2(accp[r][1]);
            float2 o;
            o.x = logf(fabsf(v.x + bps[n])     + 1e-12f);
            o.y = logf(fabsf(v.y + bps[n + 1]) + 1e-12f);
            *(float2*)(lps + (r0 + r) * GDC + n) = o;
        }
    }
    __syncthreads();

    // ---- Gumbel-argmax per (row, d)
    {
        int r = tid >> 2, d = tid & 3;
        const float* gp = gumbel + (size_t)(b0 + r) * GDC + d;
        float best = -1e30f;
        int bg = 0;
#pragma unroll
        for (int g = 0; g < GC; g++) {
            float v = lps[r * GDC + g * 4 + d] + gp[g * 4];
            if (v > best) { best = v; bg = g; }
        }
        idxs[tid] = bg;
    }
    __syncthreads();

    // ---- selection: 8 lanes per pair, 4 pairs per warp per iter, 8 iters
    const int sl = lane & 7, grp = lane >> 3;
    for (int it = 0; it < 8; it++) {
        int pp = wid * 32 + it * 4 + grp;        // pair index in [0,256)
        int r = pp >> 2, d = pp & 3;
        int head = idxs[pp] * 4 + d;
        const float4* wm = (const float4*)(Wmu  + (size_t)head * H3C);
        const float4* ws = (const float4*)(Wsig + (size_t)head * H3C);
        const float4* hv = (const float4*)(h3s + r * H3C);

        float smu = 0.f, ssg = 0.f;
#pragma unroll
        for (int j = 0; j < 6; j++) {
            int i4 = sl + 8 * j;
            float4 h = hv[i4];
            float4 m = wm[i4];
            float4 s = ws[i4];
            smu = fmaf(h.x, m.x, fmaf(h.y, m.y, fmaf(h.z, m.z, fmaf(h.w, m.w, smu))));
            ssg = fmaf(h.x, s.x, fmaf(h.y, s.y, fmaf(h.z, s.z, fmaf(h.w, s.w, ssg))));
        }
        if (sl < 2) {
            int i4 = 48 + sl;
            float4 h = hv[i4];
            float4 m = wm[i4];
            float4 s = ws[i4];
            smu = fmaf(h.x, m.x, fmaf(h.y, m.y, fmaf(h.z, m.z, fmaf(h.w, m.w, smu))));
            ssg = fmaf(h.x, s.x, fmaf(h.y, s.y, fmaf(h.z, s.z, fmaf(h.w, s.w, ssg))));
        }
#pragma unroll
        for (int off = 4; off > 0; off >>= 1) {
            smu += __shfl_xor_sync(0xffffffffu, smu, off);
            ssg += __shfl_xor_sync(0xffffffffu, ssg, off);
        }
        if (sl == 0) {
            float mu = smu + bmu[head];
            float sg = fabsf(ssg + bsig[head]);
            size_t oi = (size_t)(b0 + r) * DC + d;
            out[oi] = rnd[oi] * sg + mu;
        }
    }
}

// ---------------------------------------------------------------- launch
extern "C" void kernel_launch(void* const* d_in, const int* in_sizes, int n_in,
                              void* d_out, int out_size) {
    const float* x0   = (const float*)d_in[0];
    const float* rnd  = (const float*)d_in[1];
    const float* gum  = (const float*)d_in[2];
    const float* W1   = (const float*)d_in[3];
    const float* b1   = (const float*)d_in[4];
    const float* W2   = (const float*)d_in[5];
    const float* b2   = (const float*)d_in[6];
    const float* W3   = (const float*)d_in[7];
    const float* b3   = (const float*)d_in[8];
    const float* Wmu  = (const float*)d_in[9];
    const float* bmu  = (const float*)d_in[10];
    const float* Wsig = (const float*)d_in[11];
    const float* bsig = (const float*)d_in[12];
    const float* Wpai = (const float*)d_in[13];
    const float* bpai = (const float*)d_in[14];
    float* out = (float*)d_out;

    const size_t smF = 24704 * sizeof(float);   // 98816 B -> 2 CTAs/SM

    cudaFuncSetAttribute(k_fused, cudaFuncAttributeMaxDynamicSharedMemorySize, (int)smF);

    k_prep <<<64, 256>>>(W2, W3, Wpai);
    k_fused<<<NB / 64, 256, smF>>>(x0, W1, b1, b2, b3,
                                   gum, rnd, Wmu, bmu, Wsig, bsig, bpai, out);
}